// round 2
// baseline (speedup 1.0000x reference)
#include <cuda_runtime.h>
#include <math.h>

__global__ __launch_bounds__(128, 1)
void policy_kernel(const float* __restrict__ x,
                   const float* __restrict__ c1w, const float* __restrict__ c1b,
                   const float* __restrict__ c2w, const float* __restrict__ c2b,
                   const float* __restrict__ c3w, const float* __restrict__ c3b,
                   const float* __restrict__ e1w, const float* __restrict__ e1b,
                   const float* __restrict__ e2w, const float* __restrict__ e2b,
                   const float* __restrict__ d1w, const float* __restrict__ d1b,
                   const float* __restrict__ d2w, const float* __restrict__ d2b,
                   const float* __restrict__ d3w, const float* __restrict__ d3b,
                   const float* __restrict__ d4w, const float* __restrict__ d4b,
                   float* __restrict__ out)
{
    __shared__ float jcat[12][15];   // encoder input (also reused by dec4)
    __shared__ float c1s[6][13];
    __shared__ float dss[6][5];
    __shared__ float c2s[4][3];
    __shared__ float embin[6];       // [conv3 out x4, psi, x100]
    __shared__ float e1s[4];
    __shared__ float e2s[4];
    __shared__ float dc1[4][3];
    __shared__ float dc2[2][5];
    __shared__ float dc3[2][15];

    const int tid = threadIdx.x;

    // ---- Stage 0: build jcat + ext_obs ----
    for (int idx = tid; idx < 180; idx += 128) {
        int c = idx / 15, l = idx % 15;
        float v;
        if (c < 6) {
            int f = c * 15 + l;
            v = (f < 2) ? 0.f : x[f + 5];     // x[7 + (f-2)]
        } else {
            int f = (c - 6) * 15 + l;
            v = (f < 2) ? 0.f : x[f + 99];    // x[101 + (f-2)]
        }
        jcat[c][l] = v;
    }
    if (tid == 0) {
        float qw = x[3], qx = x[4], qy = x[5], qz = x[6];
        embin[4] = atan2f(qz, qw) - atan2f(-qx, qy);   // psi
        embin[5] = x[100];                              // obsd[:, -1]
    }
    __syncthreads();

    // ---- conv1: (12,15)->(6,13), k=3, tanh ----
    for (int idx = tid; idx < 78; idx += 128) {
        int o = idx / 13, t = idx % 13;
        float acc = c1b[o];
        const float* w = c1w + o * 36;
        #pragma unroll
        for (int i = 0; i < 12; i++) {
            #pragma unroll
            for (int j = 0; j < 3; j++)
                acc = fmaf(w[i * 3 + j], jcat[i][t + j], acc);
        }
        c1s[o][t] = tanhf(acc);
    }
    __syncthreads();

    // ---- adaptive avg pool 13 -> 5 ----
    if (tid < 30) {
        int o = tid / 5, i = tid % 5;
        int s = (i * 13) / 5;
        int e = ((i + 1) * 13 + 4) / 5;   // ceil
        float acc = 0.f;
        for (int l = s; l < e; l++) acc += c1s[o][l];
        dss[o][i] = acc / (float)(e - s);
    }
    __syncthreads();

    // ---- conv2: (6,5)->(4,3), tanh ----
    if (tid < 12) {
        int o = tid / 3, t = tid % 3;
        float acc = c2b[o];
        const float* w = c2w + o * 18;
        #pragma unroll
        for (int i = 0; i < 6; i++)
            #pragma unroll
            for (int j = 0; j < 3; j++)
                acc = fmaf(w[i * 3 + j], dss[i][t + j], acc);
        c2s[o][t] = tanhf(acc);
    }
    __syncthreads();

    // ---- conv3: (4,3)->(4,1), tanh; mean over length-1 == itself -> embin[0..3]
    if (tid < 4) {
        int o = tid;
        float acc = c3b[o];
        const float* w = c3w + o * 12;
        #pragma unroll
        for (int i = 0; i < 4; i++)
            #pragma unroll
            for (int j = 0; j < 3; j++)
                acc = fmaf(w[i * 3 + j], c2s[i][j], acc);
        embin[o] = tanhf(acc);
    }
    __syncthreads();

    // ---- emb1: 1x1 conv, 6->4, tanh ----
    if (tid < 4) {
        int o = tid;
        float acc = e1b[o];
        #pragma unroll
        for (int i = 0; i < 6; i++) acc = fmaf(e1w[o * 6 + i], embin[i], acc);
        e1s[o] = tanhf(acc);
    }
    __syncthreads();

    // ---- emb2: 1x1 conv, 4->4, tanh ----
    if (tid < 4) {
        int o = tid;
        float acc = e2b[o];
        #pragma unroll
        for (int i = 0; i < 4; i++) acc = fmaf(e2w[o * 4 + i], e1s[i], acc);
        e2s[o] = tanhf(acc);
    }
    __syncthreads();

    // ---- dec1 (convT, in4 L1 -> out4 L3): y[o,t] = b + sum_i w[i,o,t]*e2[i]
    if (tid < 12) {
        int o = tid / 3, t = tid % 3;
        float acc = d1b[o];
        #pragma unroll
        for (int i = 0; i < 4; i++)
            acc = fmaf(d1w[i * 12 + o * 3 + t], e2s[i], acc);
        dc1[o][t] = tanhf(acc);
    }
    __syncthreads();

    // ---- dec2 (convT, in4 L3 -> out2 L5) ----
    if (tid < 10) {
        int o = tid / 5, t = tid % 5;
        float acc = d2b[o];
        #pragma unroll
        for (int i = 0; i < 4; i++) {
            #pragma unroll
            for (int m = 0; m < 3; m++) {
                int s = t - m;
                if (s >= 0 && s < 3)
                    acc = fmaf(d2w[i * 6 + o * 3 + m], dc1[i][s], acc);
            }
        }
        dc2[o][t] = tanhf(acc);
    }
    __syncthreads();

    // ---- upsample (5->13 via UP idx) fused into dec3 (convT, in2 L13 -> out2 L15)
    if (tid < 30) {
        int o = tid / 15, t = tid % 15;
        const int UP[13] = {0,0,0,1,1,1,2,2,3,3,3,4,4};
        float acc = d3b[o];
        #pragma unroll
        for (int i = 0; i < 2; i++) {
            #pragma unroll
            for (int m = 0; m < 3; m++) {
                int s = t - m;
                if (s >= 0 && s < 13)
                    acc = fmaf(d3w[i * 6 + o * 3 + m], dc2[i][UP[s]], acc);
            }
        }
        dc3[o][t] = tanhf(acc);
    }
    __syncthreads();

    // ---- dec4 (convT, in14 L15 -> out6 L15, pad=1), input = [dc3(2ch); jcat(12ch)]
    // y[o,t] = b + sum_i sum_m w[i,o,m] * in[i, t+1-m]
    for (int idx = tid; idx < 90; idx += 128) {
        int o = idx / 15, t = idx % 15;
        float acc = d4b[o];
        #pragma unroll
        for (int m = 0; m < 3; m++) {
            int s = t + 1 - m;
            if (s >= 0 && s < 15) {
                #pragma unroll
                for (int i = 0; i < 2; i++)
                    acc = fmaf(d4w[i * 18 + o * 3 + m], dc3[i][s], acc);
                #pragma unroll
                for (int i = 2; i < 14; i++)
                    acc = fmaf(d4w[i * 18 + o * 3 + m], jcat[i - 2][s], acc);
            }
        }
        int flat = o * 15 + t;
        if (flat >= 2) out[flat - 2] = acc;   // acts[:, 2:]
    }
}

extern "C" void kernel_launch(void* const* d_in, const int* in_sizes, int n_in,
                              void* d_out, int out_size) {
    (void)in_sizes; (void)n_in; (void)out_size;
    policy_kernel<<<1, 128>>>(
        (const float*)d_in[0],
        (const float*)d_in[1],  (const float*)d_in[2],
        (const float*)d_in[3],  (const float*)d_in[4],
        (const float*)d_in[5],  (const float*)d_in[6],
        (const float*)d_in[7],  (const float*)d_in[8],
        (const float*)d_in[9],  (const float*)d_in[10],
        (const float*)d_in[11], (const float*)d_in[12],
        (const float*)d_in[13], (const float*)d_in[14],
        (const float*)d_in[15], (const float*)d_in[16],
        (const float*)d_in[17], (const float*)d_in[18],
        (float*)d_out);
}

// round 3
// speedup vs baseline: 1.0295x; 1.0295x over previous
#include <cuda_runtime.h>
#include <math.h>

// Branch-free fast tanh: 1 - 2/(1 + 2^(2*log2e*x)). Saturates correctly for |x| large.
__device__ __forceinline__ float ftanh(float x) {
    float e;
    asm("ex2.approx.f32 %0, %1;" : "=f"(e) : "f"(x * 2.885390081777927f)); // 2/ln(2)
    float r;
    asm("rcp.approx.f32 %0, %1;" : "=f"(r) : "f"(e + 1.0f));
    return fmaf(-2.0f, r, 1.0f);
}

// Shared weight arena offsets (floats)
#define O_C1W 0      // 216
#define O_C1B 216    // 6
#define O_C2W 222    // 72
#define O_C2B 294    // 4
#define O_C3W 298    // 48
#define O_C3B 346    // 4
#define O_E1W 350    // 24
#define O_E1B 374    // 4
#define O_E2W 378    // 16
#define O_E2B 394    // 4
#define O_D1W 398    // 48
#define O_D1B 446    // 4
#define O_D2W 450    // 24
#define O_D2B 474    // 2
#define O_D3W 476    // 12
#define O_D3B 488    // 2
#define O_D4W 490    // 252
#define O_D4B 742    // 6
#define W_TOTAL 748

__global__ __launch_bounds__(128, 1)
void policy_kernel(const float* __restrict__ x,
                   const float* __restrict__ c1w, const float* __restrict__ c1b,
                   const float* __restrict__ c2w, const float* __restrict__ c2b,
                   const float* __restrict__ c3w, const float* __restrict__ c3b,
                   const float* __restrict__ e1w, const float* __restrict__ e1b,
                   const float* __restrict__ e2w, const float* __restrict__ e2b,
                   const float* __restrict__ d1w, const float* __restrict__ d1b,
                   const float* __restrict__ d2w, const float* __restrict__ d2b,
                   const float* __restrict__ d3w, const float* __restrict__ d3b,
                   const float* __restrict__ d4w, const float* __restrict__ d4b,
                   float* __restrict__ out)
{
    __shared__ float W[W_TOTAL];
    __shared__ float jcat[12][15];
    __shared__ float c1s[6][13];
    __shared__ float dss[6][5];
    __shared__ float c2s[4][3];
    __shared__ float embin[6];
    __shared__ float e1s[4];
    __shared__ float e2s[4];
    __shared__ float dc1[4][3];
    __shared__ float dc2[2][5];
    __shared__ float dc3[2][15];

    const int tid = threadIdx.x;

    // ---- Stage 0: prefetch ALL weights + build jcat + ext_obs (one mem round-trip)
    #define CP(off, src, n) for (int i = tid; i < (n); i += 128) W[(off) + i] = src[i];
    CP(O_C1W, c1w, 216) CP(O_C1B, c1b, 6)
    CP(O_C2W, c2w, 72)  CP(O_C2B, c2b, 4)
    CP(O_C3W, c3w, 48)  CP(O_C3B, c3b, 4)
    CP(O_E1W, e1w, 24)  CP(O_E1B, e1b, 4)
    CP(O_E2W, e2w, 16)  CP(O_E2B, e2b, 4)
    CP(O_D1W, d1w, 48)  CP(O_D1B, d1b, 4)
    CP(O_D2W, d2w, 24)  CP(O_D2B, d2b, 2)
    CP(O_D3W, d3w, 12)  CP(O_D3B, d3b, 2)
    CP(O_D4W, d4w, 252) CP(O_D4B, d4b, 6)
    #undef CP

    for (int idx = tid; idx < 180; idx += 128) {
        int c = idx / 15, l = idx % 15;
        float v;
        if (c < 6) {
            int f = c * 15 + l;
            v = (f < 2) ? 0.f : x[f + 5];      // x[7 + (f-2)]
        } else {
            int f = (c - 6) * 15 + l;
            v = (f < 2) ? 0.f : x[f + 99];     // x[101 + (f-2)]
        }
        jcat[c][l] = v;
    }
    if (tid == 0) {
        float qw = x[3], qx = x[4], qy = x[5], qz = x[6];
        embin[4] = atan2f(qz, qw) - atan2f(-qx, qy);
        embin[5] = x[100];
    }
    __syncthreads();

    // ---- conv1: (12,15)->(6,13), k=3, tanh
    for (int idx = tid; idx < 78; idx += 128) {
        int o = idx / 13, t = idx % 13;
        float acc = W[O_C1B + o];
        const float* w = &W[O_C1W + o * 36];
        #pragma unroll
        for (int i = 0; i < 12; i++)
            #pragma unroll
            for (int j = 0; j < 3; j++)
                acc = fmaf(w[i * 3 + j], jcat[i][t + j], acc);
        c1s[o][t] = ftanh(acc);
    }
    __syncthreads();

    // ---- adaptive avg pool 13 -> 5
    if (tid < 30) {
        int o = tid / 5, i = tid % 5;
        int s = (i * 13) / 5;
        int e = ((i + 1) * 13 + 4) / 5;
        float acc = 0.f;
        for (int l = s; l < e; l++) acc += c1s[o][l];
        dss[o][i] = acc / (float)(e - s);
    }
    __syncthreads();

    // ---- conv2: (6,5)->(4,3), tanh
    if (tid < 12) {
        int o = tid / 3, t = tid % 3;
        float acc = W[O_C2B + o];
        const float* w = &W[O_C2W + o * 18];
        #pragma unroll
        for (int i = 0; i < 6; i++)
            #pragma unroll
            for (int j = 0; j < 3; j++)
                acc = fmaf(w[i * 3 + j], dss[i][t + j], acc);
        c2s[o][t] = ftanh(acc);
    }
    __syncthreads();

    // ---- conv3: (4,3)->(4,1), tanh; mean over L=1 is identity
    if (tid < 4) {
        int o = tid;
        float acc = W[O_C3B + o];
        const float* w = &W[O_C3W + o * 12];
        #pragma unroll
        for (int i = 0; i < 4; i++)
            #pragma unroll
            for (int j = 0; j < 3; j++)
                acc = fmaf(w[i * 3 + j], c2s[i][j], acc);
        embin[o] = ftanh(acc);
    }
    __syncthreads();

    // ---- emb1: 1x1 conv 6->4, tanh
    if (tid < 4) {
        int o = tid;
        float acc = W[O_E1B + o];
        #pragma unroll
        for (int i = 0; i < 6; i++) acc = fmaf(W[O_E1W + o * 6 + i], embin[i], acc);
        e1s[o] = ftanh(acc);
    }
    __syncthreads();

    // ---- emb2: 1x1 conv 4->4, tanh
    if (tid < 4) {
        int o = tid;
        float acc = W[O_E2B + o];
        #pragma unroll
        for (int i = 0; i < 4; i++) acc = fmaf(W[O_E2W + o * 4 + i], e1s[i], acc);
        e2s[o] = ftanh(acc);
    }
    __syncthreads();

    // ---- dec1 (convT, 4ch L1 -> 4ch L3): y[o,t] = b + sum_i w[i,o,t]*e2[i]
    if (tid < 12) {
        int o = tid / 3, t = tid % 3;
        float acc = W[O_D1B + o];
        #pragma unroll
        for (int i = 0; i < 4; i++)
            acc = fmaf(W[O_D1W + i * 12 + o * 3 + t], e2s[i], acc);
        dc1[o][t] = ftanh(acc);
    }
    __syncthreads();

    // ---- dec2 (convT, 4ch L3 -> 2ch L5)
    if (tid < 10) {
        int o = tid / 5, t = tid % 5;
        float acc = W[O_D2B + o];
        #pragma unroll
        for (int i = 0; i < 4; i++)
            #pragma unroll
            for (int m = 0; m < 3; m++) {
                int s = t - m;
                if (s >= 0 && s < 3)
                    acc = fmaf(W[O_D2W + i * 6 + o * 3 + m], dc1[i][s], acc);
            }
        dc2[o][t] = ftanh(acc);
    }
    __syncthreads();

    // ---- upsample(5->13) fused into dec3 (convT, 2ch L13 -> 2ch L15)
    if (tid < 30) {
        int o = tid / 15, t = tid % 15;
        const int UP[13] = {0,0,0,1,1,1,2,2,3,3,3,4,4};
        float acc = W[O_D3B + o];
        #pragma unroll
        for (int i = 0; i < 2; i++)
            #pragma unroll
            for (int m = 0; m < 3; m++) {
                int s = t - m;
                if (s >= 0 && s < 13)
                    acc = fmaf(W[O_D3W + i * 6 + o * 3 + m], dc2[i][UP[s]], acc);
            }
        dc3[o][t] = ftanh(acc);
    }
    __syncthreads();

    // ---- dec4 (convT, 14ch L15 -> 6ch L15, pad=1), input = [dc3(2); jcat(12)]
    for (int idx = tid; idx < 90; idx += 128) {
        int o = idx / 15, t = idx % 15;
        float acc = W[O_D4B + o];
        #pragma unroll
        for (int m = 0; m < 3; m++) {
            int s = t + 1 - m;
            if (s >= 0 && s < 15) {
                #pragma unroll
                for (int i = 0; i < 2; i++)
                    acc = fmaf(W[O_D4W + i * 18 + o * 3 + m], dc3[i][s], acc);
                #pragma unroll
                for (int i = 2; i < 14; i++)
                    acc = fmaf(W[O_D4W + i * 18 + o * 3 + m], jcat[i - 2][s], acc);
            }
        }
        int flat = o * 15 + t;
        if (flat >= 2) out[flat - 2] = acc;
    }
}

extern "C" void kernel_launch(void* const* d_in, const int* in_sizes, int n_in,
                              void* d_out, int out_size) {
    (void)in_sizes; (void)n_in; (void)out_size;
    policy_kernel<<<1, 128>>>(
        (const float*)d_in[0],
        (const float*)d_in[1],  (const float*)d_in[2],
        (const float*)d_in[3],  (const float*)d_in[4],
        (const float*)d_in[5],  (const float*)d_in[6],
        (const float*)d_in[7],  (const float*)d_in[8],
        (const float*)d_in[9],  (const float*)d_in[10],
        (const float*)d_in[11], (const float*)d_in[12],
        (const float*)d_in[13], (const float*)d_in[14],
        (const float*)d_in[15], (const float*)d_in[16],
        (const float*)d_in[17], (const float*)d_in[18],
        (float*)d_out);
}